// round 7
// baseline (speedup 1.0000x reference)
#include <cuda_runtime.h>
#include <cuda_bf16.h>
#include <cuda_fp8.h>
#include <math.h>

// ----- scratch (no allocations allowed) -----
#define NODE_CAP 131072
__device__ float g_node_sum[NODE_CAP];
// fp8(e4m3) copies of Q,K: one row = 64 fp8 = 64 B = 4 uint4
__device__ uint4 gQ8[NODE_CAP * 4];
__device__ uint4 gK8[NODE_CAP * 4];

__device__ __forceinline__ unsigned pack4_fp8(float4 a) {
    unsigned short lo = __nv_cvt_float2_to_fp8x2(make_float2(a.x, a.y), __NV_SATFINITE, __NV_E4M3);
    unsigned short hi = __nv_cvt_float2_to_fp8x2(make_float2(a.z, a.w), __NV_SATFINITE, __NV_E4M3);
    return (unsigned)lo | ((unsigned)hi << 16);
}

// fp32 -> fp8 conversion, one uint4 output per thread. First total4 threads do Q,
// next total4 do K. Fused zeroing of g_node_sum and out.
__global__ void convert_zero_kernel(const float4* __restrict__ Q,
                                    const float4* __restrict__ K,
                                    float* __restrict__ out,
                                    int total4, int num_nodes, int num_graphs) {
    int i = blockIdx.x * blockDim.x + threadIdx.x;
    if (i >= 2 * total4) return;
    if (i < num_nodes) g_node_sum[i] = 0.0f;
    if (i < num_graphs) out[i] = 0.0f;

    const float4* src;
    uint4* dst;
    int idx;
    if (i < total4) { src = Q; dst = gQ8; idx = i; }
    else            { src = K; dst = gK8; idx = i - total4; }

    const float4* p = src + idx * 4;
    float4 a0 = p[0], a1 = p[1], a2 = p[2], a3 = p[3];
    uint4 o;
    o.x = pack4_fp8(a0); o.y = pack4_fp8(a1);
    o.z = pack4_fp8(a2); o.w = pack4_fp8(a3);
    dst[idx] = o;
}

__device__ __forceinline__ float dot_fp8_u4(uint4 q, uint4 k) {
    __half2 acc = __floats2half2_rn(0.0f, 0.0f);
    #pragma unroll
    for (int j = 0; j < 4; j++) {
        unsigned qw = (&q.x)[j];
        unsigned kw = (&k.x)[j];
        __half2_raw q0 = __nv_cvt_fp8x2_to_halfraw2((__nv_fp8x2_storage_t)(qw & 0xffffu), __NV_E4M3);
        __half2_raw q1 = __nv_cvt_fp8x2_to_halfraw2((__nv_fp8x2_storage_t)(qw >> 16),     __NV_E4M3);
        __half2_raw k0 = __nv_cvt_fp8x2_to_halfraw2((__nv_fp8x2_storage_t)(kw & 0xffffu), __NV_E4M3);
        __half2_raw k1 = __nv_cvt_fp8x2_to_halfraw2((__nv_fp8x2_storage_t)(kw >> 16),     __NV_E4M3);
        acc = __hfma2(*(__half2*)&q0, *(__half2*)&k0, acc);
        acc = __hfma2(*(__half2*)&q1, *(__half2*)&k1, acc);
    }
    float2 f = __half22float2(acc);
    return f.x + f.y;
}

// 4 lanes per edge, 4 edges per slot -> 32 edges per warp. Each lane issues 8
// independent uint4 loads (MLP=8). Shuffles single-shot and unconditional.
__global__ void __launch_bounds__(256) edge_kernel(const int* __restrict__ c,
                                                   const int* __restrict__ u,
                                                   int num_edges) {
    const unsigned FULL = 0xffffffffu;
    int lane = threadIdx.x & 31;
    int grp  = lane >> 2;        // slot within warp (0..7)
    int li   = lane & 3;         // lane within 4-lane group
    int warp_id = (blockIdx.x * (blockDim.x >> 5)) + (threadIdx.x >> 5);
    int base = warp_id * 32;

    int e[4];
    bool v[4];
    int ci[4], ui[4];
    #pragma unroll
    for (int s = 0; s < 4; s++) {
        e[s] = base + s * 8 + grp;
        v[s] = (e[s] < num_edges);
        ci[s] = v[s] ? c[e[s]] : 0;
        ui[s] = v[s] ? u[e[s]] : 0;
    }

    uint4 q[4], k[4];
    #pragma unroll
    for (int s = 0; s < 4; s++) {
        q[s] = gQ8[ci[s] * 4 + li];
        k[s] = gK8[ui[s] * 4 + li];
    }

    float d[4];
    #pragma unroll
    for (int s = 0; s < 4; s++) d[s] = dot_fp8_u4(q[s], k[s]);

    #pragma unroll
    for (int s = 0; s < 4; s++) {
        d[s] += __shfl_xor_sync(FULL, d[s], 1);
        d[s] += __shfl_xor_sync(FULL, d[s], 2);
    }

    if (li == 0) {
        #pragma unroll
        for (int s = 0; s < 4; s++) {
            if (v[s]) atomicAdd(&g_node_sum[ci[s]], __expf(d[s] * 0.125f));
        }
    }
}

// Per node: lse = log(sum) (0 for empty). batch is sorted -> warp-segmented
// reduction, only segment heads hit the per-graph atomic.
__global__ void node_kernel(const int* __restrict__ batch,
                            float* __restrict__ out,
                            int num_nodes) {
    const unsigned FULL = 0xffffffffu;
    int n = blockIdx.x * blockDim.x + threadIdx.x;
    int lane = threadIdx.x & 31;

    bool valid = (n < num_nodes);
    float v = 0.0f;
    int b = -1;
    if (valid) {
        float s = g_node_sum[n];
        v = (s > 0.0f) ? __logf(s) : 0.0f;
        b = batch[n];
    }
    #pragma unroll
    for (int off = 1; off < 32; off <<= 1) {
        float ov = __shfl_down_sync(FULL, v, off);
        int   ob = __shfl_down_sync(FULL, b, off);
        if (lane + off < 32 && ob == b) v += ov;
    }
    int bprev = __shfl_up_sync(FULL, b, 1);
    bool head = (lane == 0) || (bprev != b);
    if (valid && head) {
        atomicAdd(&out[b], v);
    }
}

extern "C" void kernel_launch(void* const* d_in, const int* in_sizes, int n_in,
                              void* d_out, int out_size) {
    const float4* Q   = (const float4*)d_in[0];
    const float4* K   = (const float4*)d_in[1];
    const int* c      = (const int*)d_in[2];
    const int* u      = (const int*)d_in[3];
    const int* batch  = (const int*)d_in[4];

    int num_nodes  = in_sizes[0] / 64;
    int num_edges  = in_sizes[2];
    int num_graphs = out_size;
    float* out = (float*)d_out;

    // fp32 -> fp8 conversion of Q and K, fused with zero of node_sum + out
    {
        int total4 = num_nodes * 4;
        int total = 2 * total4;
        convert_zero_kernel<<<(total + 255) / 256, 256>>>(Q, K, out, total4,
                                                          num_nodes, num_graphs);
    }
    // edges: 4 lanes per edge, 32 edges per warp (4 per slot, MLP=8)
    {
        int threads = 256;                         // 8 warps -> 256 edges per block
        int edges_per_block = (threads / 32) * 32;
        int blocks = (num_edges + edges_per_block - 1) / edges_per_block;
        edge_kernel<<<blocks, threads>>>(c, u, num_edges);
    }
    // nodes -> per-graph energy (warp-aggregated atomics)
    {
        int blocks = (num_nodes + 511) / 512;
        node_kernel<<<blocks, 512>>>(batch, out, num_nodes);
    }
}

// round 8
// speedup vs baseline: 1.6857x; 1.6857x over previous
#include <cuda_runtime.h>
#include <cuda_bf16.h>
#include <cuda_fp8.h>
#include <math.h>

// ----- scratch (no allocations allowed) -----
#define NODE_CAP 131072
__device__ float g_node_sum[NODE_CAP];
// fp8(e4m3) copies of Q,K: one row = 64 fp8 = 64 B = 4 uint4
__device__ uint4 gQ8[NODE_CAP * 4];
__device__ uint4 gK8[NODE_CAP * 4];

__device__ __forceinline__ unsigned pack4_fp8(float4 a) {
    unsigned short lo = __nv_cvt_float2_to_fp8x2(make_float2(a.x, a.y), __NV_SATFINITE, __NV_E4M3);
    unsigned short hi = __nv_cvt_float2_to_fp8x2(make_float2(a.z, a.w), __NV_SATFINITE, __NV_E4M3);
    return (unsigned)lo | ((unsigned)hi << 16);
}

// fp32 -> fp8 conversion (16 floats of Q and K per index) fused with zeroing of
// g_node_sum and out. Grid-stride over total4 = num_nodes*4 with a wave-balanced
// grid (148 SMs x 8 CTAs) to avoid a ragged tail wave.
__global__ void convert_zero_kernel(const float4* __restrict__ Q,
                                    const float4* __restrict__ K,
                                    float* __restrict__ out,
                                    int total4, int num_nodes, int num_graphs) {
    int stride = gridDim.x * blockDim.x;
    for (int i = blockIdx.x * blockDim.x + threadIdx.x; i < total4; i += stride) {
        if (i < num_nodes) g_node_sum[i] = 0.0f;
        if (i < num_graphs) out[i] = 0.0f;
        uint4 o;
        {
            const float4* p = Q + i * 4;
            float4 a0 = p[0], a1 = p[1], a2 = p[2], a3 = p[3];
            o.x = pack4_fp8(a0); o.y = pack4_fp8(a1);
            o.z = pack4_fp8(a2); o.w = pack4_fp8(a3);
            gQ8[i] = o;
        }
        {
            const float4* p = K + i * 4;
            float4 a0 = p[0], a1 = p[1], a2 = p[2], a3 = p[3];
            o.x = pack4_fp8(a0); o.y = pack4_fp8(a1);
            o.z = pack4_fp8(a2); o.w = pack4_fp8(a3);
            gK8[i] = o;
        }
    }
}

__device__ __forceinline__ float dot_fp8_u4(uint4 q, uint4 k) {
    __half2 acc = __floats2half2_rn(0.0f, 0.0f);
    #pragma unroll
    for (int j = 0; j < 4; j++) {
        unsigned qw = (&q.x)[j];
        unsigned kw = (&k.x)[j];
        __half2_raw q0 = __nv_cvt_fp8x2_to_halfraw2((__nv_fp8x2_storage_t)(qw & 0xffffu), __NV_E4M3);
        __half2_raw q1 = __nv_cvt_fp8x2_to_halfraw2((__nv_fp8x2_storage_t)(qw >> 16),     __NV_E4M3);
        __half2_raw k0 = __nv_cvt_fp8x2_to_halfraw2((__nv_fp8x2_storage_t)(kw & 0xffffu), __NV_E4M3);
        __half2_raw k1 = __nv_cvt_fp8x2_to_halfraw2((__nv_fp8x2_storage_t)(kw >> 16),     __NV_E4M3);
        acc = __hfma2(*(__half2*)&q0, *(__half2*)&k0, acc);
        acc = __hfma2(*(__half2*)&q1, *(__half2*)&k1, acc);
    }
    float2 f = __half22float2(acc);
    return f.x + f.y;
}

// 4 lanes per edge, 2 edges per group slot -> 16 edges per warp (MLP=4: the
// measured sweet spot; MLP=8 regressed 2x via L1tex queue depth).
// Shuffles are single-shot and unconditional -> no divergence hazard.
__global__ void edge_kernel(const int* __restrict__ c,
                            const int* __restrict__ u,
                            int num_edges) {
    const unsigned FULL = 0xffffffffu;
    int lane = threadIdx.x & 31;
    int grp  = lane >> 2;        // slot within warp (0..7)
    int li   = lane & 3;         // lane within 4-lane group
    int warp_id = (blockIdx.x * (blockDim.x >> 5)) + (threadIdx.x >> 5);
    int base = warp_id * 16;
    int e0 = base + grp;
    int e1 = base + 8 + grp;

    bool v0 = (e0 < num_edges);
    bool v1 = (e1 < num_edges);

    int c0 = 0, u0 = 0, c1 = 0, u1 = 0;
    if (v0) { c0 = c[e0]; u0 = u[e0]; }
    if (v1) { c1 = c[e1]; u1 = u[e1]; }

    float d0 = 0.0f, d1 = 0.0f;
    if (v0) {
        uint4 q = gQ8[c0 * 4 + li];
        uint4 k = gK8[u0 * 4 + li];
        d0 = dot_fp8_u4(q, k);
    }
    if (v1) {
        uint4 q = gQ8[c1 * 4 + li];
        uint4 k = gK8[u1 * 4 + li];
        d1 = dot_fp8_u4(q, k);
    }

    d0 += __shfl_xor_sync(FULL, d0, 1);
    d0 += __shfl_xor_sync(FULL, d0, 2);
    d1 += __shfl_xor_sync(FULL, d1, 1);
    d1 += __shfl_xor_sync(FULL, d1, 2);

    if (li == 0) {
        if (v0) atomicAdd(&g_node_sum[c0], __expf(d0 * 0.125f));
        if (v1) atomicAdd(&g_node_sum[c1], __expf(d1 * 0.125f));
    }
}

// Per node: lse = log(sum) (0 for empty). batch is sorted -> warp-segmented
// reduction, only segment heads hit the per-graph atomic.
__global__ void node_kernel(const int* __restrict__ batch,
                            float* __restrict__ out,
                            int num_nodes) {
    const unsigned FULL = 0xffffffffu;
    int n = blockIdx.x * blockDim.x + threadIdx.x;
    int lane = threadIdx.x & 31;

    bool valid = (n < num_nodes);
    float v = 0.0f;
    int b = -1;
    if (valid) {
        float s = g_node_sum[n];
        v = (s > 0.0f) ? __logf(s) : 0.0f;
        b = batch[n];
    }
    #pragma unroll
    for (int off = 1; off < 32; off <<= 1) {
        float ov = __shfl_down_sync(FULL, v, off);
        int   ob = __shfl_down_sync(FULL, b, off);
        if (lane + off < 32 && ob == b) v += ov;
    }
    int bprev = __shfl_up_sync(FULL, b, 1);
    bool head = (lane == 0) || (bprev != b);
    if (valid && head) {
        atomicAdd(&out[b], v);
    }
}

extern "C" void kernel_launch(void* const* d_in, const int* in_sizes, int n_in,
                              void* d_out, int out_size) {
    const float4* Q   = (const float4*)d_in[0];
    const float4* K   = (const float4*)d_in[1];
    const int* c      = (const int*)d_in[2];
    const int* u      = (const int*)d_in[3];
    const int* batch  = (const int*)d_in[4];

    int num_nodes  = in_sizes[0] / 64;
    int num_edges  = in_sizes[2];
    int num_graphs = out_size;
    float* out = (float*)d_out;

    // fp32 -> fp8 conversion of Q and K, fused with zero of node_sum + out.
    // Wave-balanced grid: 148 SMs x 8 CTAs of 256 threads.
    {
        int total4 = num_nodes * 4;
        int blocks = 148 * 8;
        convert_zero_kernel<<<blocks, 256>>>(Q, K, out, total4,
                                             num_nodes, num_graphs);
    }
    // edges: 4 lanes per edge, 16 edges per warp (2 per slot, MLP=4)
    {
        int threads = 256;                         // 8 warps -> 128 edges per block
        int edges_per_block = (threads / 32) * 16;
        int blocks = (num_edges + edges_per_block - 1) / edges_per_block;
        edge_kernel<<<blocks, threads>>>(c, u, num_edges);
    }
    // nodes -> per-graph energy (warp-aggregated atomics)
    {
        int blocks = (num_nodes + 511) / 512;
        node_kernel<<<blocks, 512>>>(batch, out, num_nodes);
    }
}